// round 1
// baseline (speedup 1.0000x reference)
#include <cuda_runtime.h>
#include <cuda_bf16.h>

// out[n,h,d] = sum_j x[n,j,d] * FM[j+1,h] * Agg[0,j,h]
// (the reference's sort/gap/code machinery telescopes to this linear map)

#define S_DIM 16
#define H_DIM 4
#define N_DIM 128
#define D_DIM 512

__global__ void __launch_bounds__(128) cie_linear_kernel(
    const float* __restrict__ x,     // (N, S, D)
    const float* __restrict__ FM,    // (S+1, H)
    const float* __restrict__ Agg,   // (1, S, H)
    float* __restrict__ out)         // (N, H, D)
{
    __shared__ float W[S_DIM][H_DIM];
    const int t = threadIdx.x;           // 0..127 -> d4 index
    if (t < S_DIM * H_DIM) {
        int j = t / H_DIM, h = t % H_DIM;
        W[j][h] = FM[(j + 1) * H_DIM + h] * Agg[j * H_DIM + h];
    }
    __syncthreads();

    const int n = blockIdx.x;
    const float4* xp = reinterpret_cast<const float4*>(x + (size_t)n * S_DIM * D_DIM) + t;

    float4 acc[H_DIM];
#pragma unroll
    for (int h = 0; h < H_DIM; h++) acc[h] = make_float4(0.f, 0.f, 0.f, 0.f);

#pragma unroll
    for (int j = 0; j < S_DIM; j++) {
        float4 v = xp[j * (D_DIM / 4)];
#pragma unroll
        for (int h = 0; h < H_DIM; h++) {
            float w = W[j][h];
            acc[h].x = fmaf(v.x, w, acc[h].x);
            acc[h].y = fmaf(v.y, w, acc[h].y);
            acc[h].z = fmaf(v.z, w, acc[h].z);
            acc[h].w = fmaf(v.w, w, acc[h].w);
        }
    }

    float4* op = reinterpret_cast<float4*>(out + (size_t)n * H_DIM * D_DIM) + t;
#pragma unroll
    for (int h = 0; h < H_DIM; h++) op[h * (D_DIM / 4)] = acc[h];
}

extern "C" void kernel_launch(void* const* d_in, const int* in_sizes, int n_in,
                              void* d_out, int out_size) {
    const float* x   = (const float*)d_in[0];   // (128,16,512) f32
    const float* FM  = (const float*)d_in[1];   // (17,4) f32
    const float* Agg = (const float*)d_in[2];   // (1,16,4) f32
    // d_in[3] = source_index, unused: the table gather telescopes away.
    float* out = (float*)d_out;                 // (128,4,512) f32

    cie_linear_kernel<<<N_DIM, 128>>>(x, FM, Agg, out);
}

// round 2
// speedup vs baseline: 1.0918x; 1.0918x over previous
#include <cuda_runtime.h>
#include <cuda_bf16.h>

// out[n,h,d] = sum_j x[n,j,d] * FM[j+1,h] * Agg[0,j,h]
// (reference's sort/gap/code machinery telescopes to this linear map)
//
// R1: latency-bound fix — 4-way j-split across adjacent lanes (explicit
// 4-load batches per thread), shfl_xor reduction, 2x grid. 65K threads.

#define S_DIM 16
#define H_DIM 4
#define N_DIM 128
#define D_DIM 512

__global__ void __launch_bounds__(256) cie_linear_kernel(
    const float* __restrict__ x,     // (N, S, D)
    const float* __restrict__ FM,    // (S+1, H)
    const float* __restrict__ Agg,   // (1, S, H)
    float* __restrict__ out)         // (N, H, D)
{
    __shared__ float W[S_DIM][H_DIM];
    const int tid = threadIdx.x;
    if (tid < S_DIM * H_DIM) {
        int j = tid / H_DIM, h = tid % H_DIM;
        W[j][h] = FM[(j + 1) * H_DIM + h] * Agg[j * H_DIM + h];
    }
    __syncthreads();

    const int n     = blockIdx.x >> 1;
    const int dhalf = blockIdx.x & 1;
    const int col   = tid >> 2;        // 0..63 -> local d4 column
    const int jg    = tid & 3;         // j-group: handles j = jg*4 .. jg*4+3
    const int d4    = dhalf * 64 + col;

    const float4* xp = reinterpret_cast<const float4*>(
        x + (size_t)n * S_DIM * D_DIM) + d4;

    // Batch all 4 loads up front -> MLP=4 per thread, 16 warps/block in flight.
    float4 v[4];
#pragma unroll
    for (int jj = 0; jj < 4; jj++)
        v[jj] = xp[(jg * 4 + jj) * (D_DIM / 4)];

    float4 acc[H_DIM];
#pragma unroll
    for (int h = 0; h < H_DIM; h++) acc[h] = make_float4(0.f, 0.f, 0.f, 0.f);

#pragma unroll
    for (int jj = 0; jj < 4; jj++) {
        const int j = jg * 4 + jj;
#pragma unroll
        for (int h = 0; h < H_DIM; h++) {
            const float w = W[j][h];
            acc[h].x = fmaf(v[jj].x, w, acc[h].x);
            acc[h].y = fmaf(v[jj].y, w, acc[h].y);
            acc[h].z = fmaf(v[jj].z, w, acc[h].z);
            acc[h].w = fmaf(v[jj].w, w, acc[h].w);
        }
    }

    // Reduce the 4 j-group partials across adjacent lanes (xor 1, then 2).
#pragma unroll
    for (int m = 1; m <= 2; m <<= 1) {
#pragma unroll
        for (int h = 0; h < H_DIM; h++) {
            acc[h].x += __shfl_xor_sync(0xffffffffu, acc[h].x, m);
            acc[h].y += __shfl_xor_sync(0xffffffffu, acc[h].y, m);
            acc[h].z += __shfl_xor_sync(0xffffffffu, acc[h].z, m);
            acc[h].w += __shfl_xor_sync(0xffffffffu, acc[h].w, m);
        }
    }

    if (jg == 0) {
        float4* op = reinterpret_cast<float4*>(
            out + (size_t)n * H_DIM * D_DIM) + d4;
#pragma unroll
        for (int h = 0; h < H_DIM; h++) op[h * (D_DIM / 4)] = acc[h];
    }
}

extern "C" void kernel_launch(void* const* d_in, const int* in_sizes, int n_in,
                              void* d_out, int out_size) {
    const float* x   = (const float*)d_in[0];   // (128,16,512) f32
    const float* FM  = (const float*)d_in[1];   // (17,4) f32
    const float* Agg = (const float*)d_in[2];   // (1,16,4) f32
    // d_in[3] = source_index, unused: the table gather telescopes away.
    float* out = (float*)d_out;                 // (128,4,512) f32

    cie_linear_kernel<<<N_DIM * 2, 256>>>(x, FM, Agg, out);
}